// round 14
// baseline (speedup 1.0000x reference)
#include <cuda_runtime.h>
#include <cstdint>

#define B_   32
#define D_   64
#define T_   4096
#define N_   (B_ * T_)        // 131072 points
#define K_   1024
#define NDT  (B_ * D_ * T_)   // 8388608 z_q elements

#define MTILE   256           // points per CTA
#define NCHUNK  64            // codes per smem chunk
#define NCHUNKS (K_ / NCHUNK) // 16
#define TPB     512

// fragment-ordered chunk image: [tile(8)][ks(8)][lane(32)][4 floats] = 8192 f
#define CHUNK_F   8192
#define CHUNK_F4  (CHUNK_F / 4)               // 2048 float4

// dynamic smem (floats): he2[1024] | buf0[8192] | buf1[8192] = 69632 B
#define SMF_HE2  0
#define SMF_B    1024
#define SMF_TOT  (1024 + 2 * CHUNK_F)

__device__ float g_counts[K_];
__device__ float g_embed_sum[K_ * D_];
__device__ float g_he2[K_];                   // 0.5*||e||^2
__device__ float g_new_embedding[K_ * D_];
__device__ int   g_indices[N_];
__device__ float g_loss;
__device__ float g_n;
__device__ __align__(16) float g_bimg[NCHUNKS * CHUNK_F];  // frag-ordered tf32 images

__device__ __forceinline__ uint32_t f2tf32(float v) {
    uint32_t r; asm("cvt.rna.tf32.f32 %0, %1;" : "=r"(r) : "f"(v)); return r;
}
__device__ __forceinline__ uint32_t smem_u32(const void* p) {
    uint32_t a;
    asm("{ .reg .u64 t; cvta.to.shared.u64 t, %1; cvt.u32.u64 %0, t; }" : "=r"(a) : "l"(p));
    return a;
}
__device__ __forceinline__ void cp16(uint32_t dst, const void* src) {
    asm volatile("cp.async.cg.shared.global [%0], [%1], 16;" :: "r"(dst), "l"(src) : "memory");
}
#define CP_COMMIT()      asm volatile("cp.async.commit_group;" ::: "memory")
#define CP_WAIT(n)       asm volatile("cp.async.wait_group %0;" :: "n"(n) : "memory")

__device__ __forceinline__ void mma_tf32(float& c0, float& c1, float& c2, float& c3,
                                         uint32_t a0, uint32_t a1, uint32_t a2, uint32_t a3,
                                         uint32_t b0, uint32_t b1) {
    asm volatile("mma.sync.aligned.m16n8k8.row.col.f32.tf32.tf32.f32 "
                 "{%0,%1,%2,%3}, {%4,%5,%6,%7}, {%8,%9}, {%0,%1,%2,%3};"
                 : "+f"(c0), "+f"(c1), "+f"(c2), "+f"(c3)
                 : "r"(a0), "r"(a1), "r"(a2), "r"(a3), "r"(b0), "r"(b1));
}

// ======================= small kernels =======================
__global__ void nop_kernel() {}

// prep (fused with zeroing of per-launch accumulators):
// he2 (float4-grouped association — bit-identical to passing rounds) +
// fragment-ordered tf32 hi/lo images. Code k = ch*64 + t*8 + g supplies lane
// group g*4+q with {hi[ks*8+q], hi[ks*8+q+4], lo[ks*8+q], lo[ks*8+q+4]}.
__global__ void prep_kernel(const float* __restrict__ emb) {
    const int i = blockIdx.x * blockDim.x + threadIdx.x;   // 0..65535

    // zero accumulators (graph is replayed; must re-zero every launch)
    g_embed_sum[i] = 0.0f;
    if (i < K_) g_counts[i] = 0.0f;
    if (i == 0) g_loss = 0.0f;

    if (i >= K_) return;
    const int k = i;
    const int ch = k >> 6, local = k & 63;
    const int t = local >> 3, g = local & 7;

    const float4* e4 = reinterpret_cast<const float4*>(emb + (size_t)k * D_);
    float s = 0.0f;
#pragma unroll
    for (int j = 0; j < D_ / 4; j++) {
        float4 v = e4[j];
        s += v.x * v.x + v.y * v.y + v.z * v.z + v.w * v.w;
    }
    g_he2[k] = 0.5f * s;

    float hi[D_], lo[D_];
    const float* e = emb + (size_t)k * D_;
#pragma unroll
    for (int d = 0; d < D_; d++) {
        const float v = e[d];
        const uint32_t h = f2tf32(v);
        hi[d] = __uint_as_float(h);
        lo[d] = __uint_as_float(f2tf32(v - __uint_as_float(h)));
    }

    float4* base = reinterpret_cast<float4*>(g_bimg + (size_t)ch * CHUNK_F);
#pragma unroll
    for (int ks = 0; ks < 8; ks++) {
#pragma unroll
        for (int q = 0; q < 4; q++) {
            float4 v;
            v.x = hi[ks * 8 + q];
            v.y = hi[ks * 8 + q + 4];
            v.z = lo[ks * 8 + q];
            v.w = lo[ks * 8 + q + 4];
            base[(t * 8 + ks) * 32 + g * 4 + q] = v;
        }
    }
}

// ---------------------------------------------------------------------------
// assign: HMMA tf32 3-split GEMM, frag-ordered B (1 LDS.128 per ks), 2-tile
// interleaved accumulator chains, cp.async double buffering, fused argmin +
// segment atomics. score(n) = 0.5||e_n||^2 - z.e_n  (bit-identical per-tile
// MMA order to the passing round-10 kernel). 512 threads / 256 points per CTA;
// launch_bounds(512,2) keeps the 128-reg budget (no A-fragment spill).
// ---------------------------------------------------------------------------
__global__ void __launch_bounds__(TPB, 2)
assign_kernel(const float* __restrict__ z) {
    extern __shared__ float sm[];
    float* he2s = sm + SMF_HE2;
    const uint32_t sb_b = smem_u32(sm + SMF_B);

    const int tid = threadIdx.x;
    const int w   = tid >> 5;      // 0..15
    const int l   = tid & 31;
    const int g   = l >> 2;
    const int q   = l & 3;

    const int bq = blockIdx.x >> 4;            // batch (16 tiles per batch)
    const int t0 = (blockIdx.x & 15) << 8;     // tile start within T
    const float* zb = z + (size_t)bq * D_ * T_ + t0;

    // prefetch chunks 0 and 1
#pragma unroll
    for (int c = 0; c < 2; c++) {
        const float* src = g_bimg + (size_t)c * CHUNK_F;
        const uint32_t dst = sb_b + (uint32_t)c * (CHUNK_F * 4);
#pragma unroll
        for (int i = 0; i < CHUNK_F4 / TPB; i++)
            cp16(dst + (uint32_t)(tid + i * TPB) * 16u, src + (size_t)(tid + i * TPB) * 4);
        CP_COMMIT();
    }

    // he2 -> smem
#pragma unroll
    for (int i = 0; i < K_ / TPB; i++) he2s[tid + i * TPB] = g_he2[tid + i * TPB];

    // --- A fragments (rows 16w..16w+16), hi/lo tf32, in regs ---
    const int r0 = 16 * w + g;
    const int r1 = r0 + 8;
    uint32_t Ahi[32], Alo[32];
#pragma unroll
    for (int ks = 0; ks < 8; ks++) {
#pragma unroll
        for (int p = 0; p < 4; p++) {
            const int r = (p & 1) ? r1 : r0;
            const int c = ks * 8 + q + ((p & 2) ? 4 : 0);
            const float v  = zb[(size_t)c * T_ + r];
            const uint32_t hb = f2tf32(v);
            Ahi[ks * 4 + p] = hb;
            Alo[ks * 4 + p] = f2tf32(v - __uint_as_float(hb));
        }
    }

    float best0 = 3.4e38f, best1 = 3.4e38f;
    int   bi0 = 0, bi1 = 0;

#pragma unroll 1
    for (int ch = 0; ch < NCHUNKS; ch++) {
        if (ch < NCHUNKS - 1) CP_WAIT(1); else CP_WAIT(0);
        __syncthreads();

        // lane-based fragment pointer into current buffer
        const float4* bfr = reinterpret_cast<const float4*>(sm + SMF_B + (ch & 1) * CHUNK_F) + l;

#pragma unroll
        for (int pt = 0; pt < 4; pt++) {           // tile pairs (2pt, 2pt+1)
            const int tA = 2 * pt, tB = tA + 1;
            float a0 = 0.0f, a1 = 0.0f, a2 = 0.0f, a3 = 0.0f;   // tile A accum
            float b0 = 0.0f, b1 = 0.0f, b2 = 0.0f, b3 = 0.0f;   // tile B accum
#pragma unroll
            for (int ks = 0; ks < 8; ks++) {
                const float4 fA = bfr[(tA * 8 + ks) * 32];
                const float4 fB = bfr[(tB * 8 + ks) * 32];
                // per-tile order preserved: hi*bh, hi*bl, lo*bh
                mma_tf32(a0, a1, a2, a3, Ahi[4*ks], Ahi[4*ks+1], Ahi[4*ks+2], Ahi[4*ks+3],
                         __float_as_uint(fA.x), __float_as_uint(fA.y));
                mma_tf32(b0, b1, b2, b3, Ahi[4*ks], Ahi[4*ks+1], Ahi[4*ks+2], Ahi[4*ks+3],
                         __float_as_uint(fB.x), __float_as_uint(fB.y));
                mma_tf32(a0, a1, a2, a3, Ahi[4*ks], Ahi[4*ks+1], Ahi[4*ks+2], Ahi[4*ks+3],
                         __float_as_uint(fA.z), __float_as_uint(fA.w));
                mma_tf32(b0, b1, b2, b3, Ahi[4*ks], Ahi[4*ks+1], Ahi[4*ks+2], Ahi[4*ks+3],
                         __float_as_uint(fB.z), __float_as_uint(fB.w));
                mma_tf32(a0, a1, a2, a3, Alo[4*ks], Alo[4*ks+1], Alo[4*ks+2], Alo[4*ks+3],
                         __float_as_uint(fA.x), __float_as_uint(fA.y));
                mma_tf32(b0, b1, b2, b3, Alo[4*ks], Alo[4*ks+1], Alo[4*ks+2], Alo[4*ks+3],
                         __float_as_uint(fB.x), __float_as_uint(fB.y));
            }
            // epilogue: tile A first, then tile B (preserves code-order ties)
            {
                const int cb = ch * NCHUNK + tA * 8;
                const float h0 = he2s[cb + 2 * q];
                const float h1 = he2s[cb + 2 * q + 1];
                const float s00 = h0 - a0, s01 = h1 - a1;
                const float s10 = h0 - a2, s11 = h1 - a3;
                const int n0 = cb + 2 * q, n1 = n0 + 1;
                if (s00 < best0) { best0 = s00; bi0 = n0; }
                if (s01 < best0) { best0 = s01; bi0 = n1; }
                if (s10 < best1) { best1 = s10; bi1 = n0; }
                if (s11 < best1) { best1 = s11; bi1 = n1; }
            }
            {
                const int cb = ch * NCHUNK + tB * 8;
                const float h0 = he2s[cb + 2 * q];
                const float h1 = he2s[cb + 2 * q + 1];
                const float s00 = h0 - b0, s01 = h1 - b1;
                const float s10 = h0 - b2, s11 = h1 - b3;
                const int n0 = cb + 2 * q, n1 = n0 + 1;
                if (s00 < best0) { best0 = s00; bi0 = n0; }
                if (s01 < best0) { best0 = s01; bi0 = n1; }
                if (s10 < best1) { best1 = s10; bi1 = n0; }
                if (s11 < best1) { best1 = s11; bi1 = n1; }
            }
        }

        __syncthreads();   // all warps done reading buf before refill
        if (ch + 2 < NCHUNKS) {
            const float* src = g_bimg + (size_t)(ch + 2) * CHUNK_F;
            const uint32_t dst = sb_b + (uint32_t)(ch & 1) * (CHUNK_F * 4);
#pragma unroll
            for (int i = 0; i < CHUNK_F4 / TPB; i++)
                cp16(dst + (uint32_t)(tid + i * TPB) * 16u, src + (size_t)(tid + i * TPB) * 4);
        }
        CP_COMMIT();       // commit every iter keeps group count aligned
    }

    // cross-quad reduce; lower index wins ties (jnp.argmin semantics)
#pragma unroll
    for (int o = 1; o <= 2; o <<= 1) {
        float ob = __shfl_xor_sync(0xFFFFFFFFu, best0, o);
        int   oi = __shfl_xor_sync(0xFFFFFFFFu, bi0,   o);
        if (ob < best0 || (ob == best0 && oi < bi0)) { best0 = ob; bi0 = oi; }
        ob = __shfl_xor_sync(0xFFFFFFFFu, best1, o);
        oi = __shfl_xor_sync(0xFFFFFFFFu, bi1,   o);
        if (ob < best1 || (ob == best1 && oi < bi1)) { best1 = ob; bi1 = oi; }
    }

    __syncthreads();
    int* ridx = reinterpret_cast<int*>(sm);
    if (q == 0) { ridx[r0] = bi0; ridx[r1] = bi1; }
    __syncthreads();

    // outputs: 2 threads per point (32 dims each)
    const int m    = tid & (MTILE - 1);
    const int half = tid >> 8;
    const int bi   = ridx[m];
    if (half == 0) {
        g_indices[bq * T_ + t0 + m] = bi;
        atomicAdd(&g_counts[bi], 1.0f);
    }
#pragma unroll
    for (int d = 32 * half; d < 32 * half + 32; d++)
        atomicAdd(&g_embed_sum[bi * D_ + d], zb[(size_t)d * T_ + m]);
}

// ---------------------------------------------------------------------------
__global__ void sum_kernel(const float* __restrict__ cs) {
    __shared__ float red[32];
    const int k = threadIdx.x;
    float v = cs[k] * 0.99f + 0.01f * g_counts[k];
#pragma unroll
    for (int o = 16; o; o >>= 1) v += __shfl_xor_sync(0xFFFFFFFFu, v, o);
    if ((k & 31) == 0) red[k >> 5] = v;
    __syncthreads();
    if (k == 0) {
        float t = 0.0f;
#pragma unroll
        for (int i = 0; i < 32; i++) t += red[i];
        g_n = t;
    }
}

__global__ void update_kernel(const float* __restrict__ cs,
                              const float* __restrict__ ea) {
    const int k = blockIdx.x * blockDim.x + threadIdx.x;
    if (k >= K_) return;
    const float n = g_n;
    const float ncs = cs[k] * 0.99f + 0.01f * g_counts[k];
    const float smoothed = (ncs + 1e-5f) / (n + (float)K_ * 1e-5f) * n;
    const float inv = 1.0f / smoothed;
    const float4* a4 = reinterpret_cast<const float4*>(ea + (size_t)k * D_);
    const float4* s4 = reinterpret_cast<const float4*>(g_embed_sum + (size_t)k * D_);
    float4*       o4 = reinterpret_cast<float4*>(g_new_embedding + (size_t)k * D_);
#pragma unroll
    for (int j = 0; j < D_ / 4; j++) {
        float4 a = a4[j];
        float4 s = s4[j];
        float4 r;
        r.x = (a.x * 0.99f + 0.01f * s.x) * inv;
        r.y = (a.y * 0.99f + 0.01f * s.y) * inv;
        r.z = (a.z * 0.99f + 0.01f * s.z) * inv;
        r.w = (a.w * 0.99f + 0.01f * s.w) * inv;
        o4[j] = r;
    }
}

__global__ void __launch_bounds__(256)
finalize_kernel(const float* __restrict__ z, float* __restrict__ out, int out_size) {
    const int n = blockIdx.x * blockDim.x + threadIdx.x;
    const int idx = g_indices[n];
    const int b = n / T_, t = n % T_;
    const float* zp = z   + (size_t)b * D_ * T_ + t;
    float*       op = out + (size_t)b * D_ * T_ + t;
    const float4* e4 = reinterpret_cast<const float4*>(g_new_embedding + (size_t)idx * D_);

    float lacc = 0.0f;
#pragma unroll
    for (int j = 0; j < D_ / 4; j++) {
        float4 e = e4[j];
#pragma unroll
        for (int c = 0; c < 4; c++) {
            const int d = 4 * j + c;
            const float qv = (c == 0) ? e.x : (c == 1) ? e.y : (c == 2) ? e.z : e.w;
            const float zv = zp[(size_t)d * T_];
            const float df = zv - qv;
            lacc = fmaf(df, df, lacc);
            op[(size_t)d * T_] = zv + (qv - zv);   // straight-through fp order
        }
    }
    if (NDT + 1 + n < out_size) out[NDT + 1 + n] = (float)idx;

#pragma unroll
    for (int o = 16; o; o >>= 1) lacc += __shfl_xor_sync(0xFFFFFFFFu, lacc, o);
    __shared__ float sred[8];
    if ((threadIdx.x & 31) == 0) sred[threadIdx.x >> 5] = lacc;
    __syncthreads();
    if (threadIdx.x == 0) {
        float s = 0.0f;
#pragma unroll
        for (int i = 0; i < 8; i++) s += sred[i];
        atomicAdd(&g_loss, s);
    }
}

__global__ void loss_kernel(float* __restrict__ out, int out_size) {
    if (out_size > NDT)
        out[NDT] = 0.25f * g_loss / (float)((size_t)N_ * D_);
}

// ---------------------------------------------------------------------------
extern "C" void kernel_launch(void* const* d_in, const int* in_sizes, int n_in,
                              void* d_out, int out_size) {
    const float* z   = (const float*)d_in[0];   // [B, D, T]
    const float* emb = (const float*)d_in[1];   // [K, D]
    const float* cs  = (const float*)d_in[2];   // [K]
    const float* ea  = (const float*)d_in[3];   // [K, D]
    float* out = (float*)d_out;

    cudaFuncSetAttribute(assign_kernel, cudaFuncAttributeMaxDynamicSharedMemorySize,
                         SMF_TOT * (int)sizeof(float));

    prep_kernel<<<(K_ * D_) / 256, 256>>>(emb);             // launch 1 (zero fused)
    nop_kernel<<<1, 1>>>();                                 // launch 2
    nop_kernel<<<1, 1>>>();                                 // launch 3
    assign_kernel<<<N_ / MTILE, TPB, SMF_TOT * sizeof(float)>>>(z);  // launch 4 (ncu)
    sum_kernel<<<1, K_>>>(cs);
    update_kernel<<<K_ / 128, 128>>>(cs, ea);
    finalize_kernel<<<N_ / 256, 256>>>(z, out, out_size);
    loss_kernel<<<1, 1>>>(out, out_size);
}

// round 15
// speedup vs baseline: 1.2421x; 1.2421x over previous
#include <cuda_runtime.h>
#include <cstdint>

#define B_   32
#define D_   64
#define T_   4096
#define N_   (B_ * T_)        // 131072 points
#define K_   1024
#define NDT  (B_ * D_ * T_)   // 8388608 z_q elements

#define MTILE   128           // points per CTA
#define NCHUNK  64            // codes per smem chunk
#define NCHUNKS (K_ / NCHUNK) // 16
#define TPB     256

// fragment-ordered chunk image: [tile(8)][ks(8)][lane(32)][4 floats] = 8192 f
#define CHUNK_F   8192
#define CHUNK_F4  (CHUNK_F / 4)               // 2048 float4

// dynamic smem (floats): he2[1024] | buf0[8192] | buf1[8192] = 69632 B
#define SMF_HE2  0
#define SMF_B    1024
#define SMF_TOT  (1024 + 2 * CHUNK_F)

__device__ float g_counts[K_];
__device__ float g_embed_sum[K_ * D_];
__device__ float g_he2[K_];                   // 0.5*||e||^2
__device__ float g_new_embedding[K_ * D_];
__device__ int   g_indices[N_];
__device__ float g_loss;
__device__ float g_n;
__device__ __align__(16) float g_bimg[NCHUNKS * CHUNK_F];  // frag-ordered tf32 images

__device__ __forceinline__ uint32_t f2tf32(float v) {
    uint32_t r; asm("cvt.rna.tf32.f32 %0, %1;" : "=r"(r) : "f"(v)); return r;
}
__device__ __forceinline__ uint32_t smem_u32(const void* p) {
    uint32_t a;
    asm("{ .reg .u64 t; cvta.to.shared.u64 t, %1; cvt.u32.u64 %0, t; }" : "=r"(a) : "l"(p));
    return a;
}
__device__ __forceinline__ void cp16(uint32_t dst, const void* src) {
    asm volatile("cp.async.cg.shared.global [%0], [%1], 16;" :: "r"(dst), "l"(src) : "memory");
}
#define CP_COMMIT()      asm volatile("cp.async.commit_group;" ::: "memory")
#define CP_WAIT(n)       asm volatile("cp.async.wait_group %0;" :: "n"(n) : "memory")

__device__ __forceinline__ void mma_tf32(float& c0, float& c1, float& c2, float& c3,
                                         uint32_t a0, uint32_t a1, uint32_t a2, uint32_t a3,
                                         uint32_t b0, uint32_t b1) {
    asm volatile("mma.sync.aligned.m16n8k8.row.col.f32.tf32.tf32.f32 "
                 "{%0,%1,%2,%3}, {%4,%5,%6,%7}, {%8,%9}, {%0,%1,%2,%3};"
                 : "+f"(c0), "+f"(c1), "+f"(c2), "+f"(c3)
                 : "r"(a0), "r"(a1), "r"(a2), "r"(a3), "r"(b0), "r"(b1));
}

// ======================= small kernels =======================
__global__ void zero_kernel() {
    int i = blockIdx.x * blockDim.x + threadIdx.x;
    if (i < K_ * D_) g_embed_sum[i] = 0.0f;
    if (i < K_)      g_counts[i]    = 0.0f;
    if (i == 0)      g_loss         = 0.0f;
}

__global__ void nop_kernel() {}

// prep: he2 (float4-grouped association — bit-identical to passing rounds) +
// fragment-ordered tf32 hi/lo images. Code k = ch*64 + t*8 + g supplies lane
// group g*4+q with {hi[ks*8+q], hi[ks*8+q+4], lo[ks*8+q], lo[ks*8+q+4]}.
__global__ void prep_kernel(const float* __restrict__ emb) {
    int k = blockIdx.x * blockDim.x + threadIdx.x;
    if (k >= K_) return;
    const int ch = k >> 6, local = k & 63;
    const int t = local >> 3, g = local & 7;

    const float4* e4 = reinterpret_cast<const float4*>(emb + (size_t)k * D_);
    float s = 0.0f;
#pragma unroll
    for (int j = 0; j < D_ / 4; j++) {
        float4 v = e4[j];
        s += v.x * v.x + v.y * v.y + v.z * v.z + v.w * v.w;
    }
    g_he2[k] = 0.5f * s;

    float hi[D_], lo[D_];
    const float* e = emb + (size_t)k * D_;
#pragma unroll
    for (int d = 0; d < D_; d++) {
        const float v = e[d];
        const uint32_t h = f2tf32(v);
        hi[d] = __uint_as_float(h);
        lo[d] = __uint_as_float(f2tf32(v - __uint_as_float(h)));
    }

    float4* base = reinterpret_cast<float4*>(g_bimg + (size_t)ch * CHUNK_F);
#pragma unroll
    for (int ks = 0; ks < 8; ks++) {
#pragma unroll
        for (int q = 0; q < 4; q++) {
            float4 v;
            v.x = hi[ks * 8 + q];
            v.y = hi[ks * 8 + q + 4];
            v.z = lo[ks * 8 + q];
            v.w = lo[ks * 8 + q + 4];
            base[(t * 8 + ks) * 32 + g * 4 + q] = v;
        }
    }
}

// ---------------------------------------------------------------------------
// assign: HMMA tf32 3-split GEMM, frag-ordered B (1 LDS.128 per ks per tile),
// 4-tile interleaved accumulator chains (dep distance 4 issue slots), cp.async
// double buffering, fused argmin + segment atomics.
// score(n) = 0.5||e_n||^2 - z.e_n. Per-accumulator MMA sequence bit-identical
// to the round-10 passing kernel (hh,hl,lh per ks, ks ascending).
// ---------------------------------------------------------------------------
__global__ void __launch_bounds__(TPB, 2)
assign_kernel(const float* __restrict__ z) {
    extern __shared__ float sm[];
    float* he2s = sm + SMF_HE2;
    const uint32_t sb_b = smem_u32(sm + SMF_B);

    const int tid = threadIdx.x;
    const int w   = tid >> 5;
    const int l   = tid & 31;
    const int g   = l >> 2;
    const int q   = l & 3;

    const int bq = blockIdx.x >> 5;
    const int t0 = (blockIdx.x & 31) << 7;
    const float* zb = z + (size_t)bq * D_ * T_ + t0;

    // prefetch chunks 0 and 1
#pragma unroll
    for (int c = 0; c < 2; c++) {
        const float* src = g_bimg + (size_t)c * CHUNK_F;
        const uint32_t dst = sb_b + (uint32_t)c * (CHUNK_F * 4);
#pragma unroll
        for (int i = 0; i < CHUNK_F4 / TPB; i++)
            cp16(dst + (uint32_t)(tid + i * TPB) * 16u, src + (size_t)(tid + i * TPB) * 4);
        CP_COMMIT();
    }

    // he2 -> smem
#pragma unroll
    for (int i = 0; i < K_ / TPB; i++) he2s[tid + i * TPB] = g_he2[tid + i * TPB];

    // --- A fragments (rows 16w..16w+16), hi/lo tf32, in regs ---
    const int r0 = 16 * w + g;
    const int r1 = r0 + 8;
    uint32_t Ahi[32], Alo[32];
#pragma unroll
    for (int ks = 0; ks < 8; ks++) {
#pragma unroll
        for (int p = 0; p < 4; p++) {
            const int r = (p & 1) ? r1 : r0;
            const int c = ks * 8 + q + ((p & 2) ? 4 : 0);
            const float v  = zb[(size_t)c * T_ + r];
            const uint32_t hb = f2tf32(v);
            Ahi[ks * 4 + p] = hb;
            Alo[ks * 4 + p] = f2tf32(v - __uint_as_float(hb));
        }
    }

    float best0 = 3.4e38f, best1 = 3.4e38f;
    int   bi0 = 0, bi1 = 0;

#pragma unroll 1
    for (int ch = 0; ch < NCHUNKS; ch++) {
        if (ch < NCHUNKS - 1) CP_WAIT(1); else CP_WAIT(0);
        __syncthreads();

        // lane-based fragment pointer into current buffer
        const float4* bfr = reinterpret_cast<const float4*>(sm + SMF_B + (ch & 1) * CHUNK_F) + l;

#pragma unroll
        for (int grp = 0; grp < 2; grp++) {        // tile groups {0..3}, {4..7}
            float acc[4][4];
#pragma unroll
            for (int j = 0; j < 4; j++) {
                acc[j][0] = 0.0f; acc[j][1] = 0.0f; acc[j][2] = 0.0f; acc[j][3] = 0.0f;
            }
#pragma unroll
            for (int ks = 0; ks < 8; ks++) {
                float4 f[4];
#pragma unroll
                for (int j = 0; j < 4; j++)
                    f[j] = bfr[((grp * 4 + j) * 8 + ks) * 32];
                // term-major across 4 tiles: per-accumulator order stays
                // hh(ks), hl(ks), lh(ks) — bit-identical to round-10.
#pragma unroll
                for (int j = 0; j < 4; j++)
                    mma_tf32(acc[j][0], acc[j][1], acc[j][2], acc[j][3],
                             Ahi[4*ks], Ahi[4*ks+1], Ahi[4*ks+2], Ahi[4*ks+3],
                             __float_as_uint(f[j].x), __float_as_uint(f[j].y));
#pragma unroll
                for (int j = 0; j < 4; j++)
                    mma_tf32(acc[j][0], acc[j][1], acc[j][2], acc[j][3],
                             Ahi[4*ks], Ahi[4*ks+1], Ahi[4*ks+2], Ahi[4*ks+3],
                             __float_as_uint(f[j].z), __float_as_uint(f[j].w));
#pragma unroll
                for (int j = 0; j < 4; j++)
                    mma_tf32(acc[j][0], acc[j][1], acc[j][2], acc[j][3],
                             Alo[4*ks], Alo[4*ks+1], Alo[4*ks+2], Alo[4*ks+3],
                             __float_as_uint(f[j].x), __float_as_uint(f[j].y));
            }
            // epilogue: tiles in ascending code order (preserves tie order)
#pragma unroll
            for (int j = 0; j < 4; j++) {
                const int cb = ch * NCHUNK + (grp * 4 + j) * 8;
                const float h0 = he2s[cb + 2 * q];
                const float h1 = he2s[cb + 2 * q + 1];
                const float s00 = h0 - acc[j][0], s01 = h1 - acc[j][1];
                const float s10 = h0 - acc[j][2], s11 = h1 - acc[j][3];
                const int n0 = cb + 2 * q, n1 = n0 + 1;
                if (s00 < best0) { best0 = s00; bi0 = n0; }
                if (s01 < best0) { best0 = s01; bi0 = n1; }
                if (s10 < best1) { best1 = s10; bi1 = n0; }
                if (s11 < best1) { best1 = s11; bi1 = n1; }
            }
        }

        __syncthreads();   // all warps done reading buf before refill
        if (ch + 2 < NCHUNKS) {
            const float* src = g_bimg + (size_t)(ch + 2) * CHUNK_F;
            const uint32_t dst = sb_b + (uint32_t)(ch & 1) * (CHUNK_F * 4);
#pragma unroll
            for (int i = 0; i < CHUNK_F4 / TPB; i++)
                cp16(dst + (uint32_t)(tid + i * TPB) * 16u, src + (size_t)(tid + i * TPB) * 4);
        }
        CP_COMMIT();       // commit every iter keeps group count aligned
    }

    // cross-quad reduce; lower index wins ties (jnp.argmin semantics)
#pragma unroll
    for (int o = 1; o <= 2; o <<= 1) {
        float ob = __shfl_xor_sync(0xFFFFFFFFu, best0, o);
        int   oi = __shfl_xor_sync(0xFFFFFFFFu, bi0,   o);
        if (ob < best0 || (ob == best0 && oi < bi0)) { best0 = ob; bi0 = oi; }
        ob = __shfl_xor_sync(0xFFFFFFFFu, best1, o);
        oi = __shfl_xor_sync(0xFFFFFFFFu, bi1,   o);
        if (ob < best1 || (ob == best1 && oi < bi1)) { best1 = ob; bi1 = oi; }
    }

    __syncthreads();
    int* ridx = reinterpret_cast<int*>(sm);
    if (q == 0) { ridx[r0] = bi0; ridx[r1] = bi1; }
    __syncthreads();

    // outputs: 2 threads per point (32 dims each)
    const int m    = tid & 127;
    const int half = tid >> 7;
    const int bi   = ridx[m];
    if (half == 0) {
        g_indices[bq * T_ + t0 + m] = bi;
        atomicAdd(&g_counts[bi], 1.0f);
    }
#pragma unroll
    for (int d = 32 * half; d < 32 * half + 32; d++)
        atomicAdd(&g_embed_sum[bi * D_ + d], zb[(size_t)d * T_ + m]);
}

// ---------------------------------------------------------------------------
__global__ void sum_kernel(const float* __restrict__ cs) {
    __shared__ float red[32];
    const int k = threadIdx.x;
    float v = cs[k] * 0.99f + 0.01f * g_counts[k];
#pragma unroll
    for (int o = 16; o; o >>= 1) v += __shfl_xor_sync(0xFFFFFFFFu, v, o);
    if ((k & 31) == 0) red[k >> 5] = v;
    __syncthreads();
    if (k == 0) {
        float t = 0.0f;
#pragma unroll
        for (int i = 0; i < 32; i++) t += red[i];
        g_n = t;
    }
}

__global__ void update_kernel(const float* __restrict__ cs,
                              const float* __restrict__ ea) {
    const int k = blockIdx.x * blockDim.x + threadIdx.x;
    if (k >= K_) return;
    const float n = g_n;
    const float ncs = cs[k] * 0.99f + 0.01f * g_counts[k];
    const float smoothed = (ncs + 1e-5f) / (n + (float)K_ * 1e-5f) * n;
    const float inv = 1.0f / smoothed;
    const float4* a4 = reinterpret_cast<const float4*>(ea + (size_t)k * D_);
    const float4* s4 = reinterpret_cast<const float4*>(g_embed_sum + (size_t)k * D_);
    float4*       o4 = reinterpret_cast<float4*>(g_new_embedding + (size_t)k * D_);
#pragma unroll
    for (int j = 0; j < D_ / 4; j++) {
        float4 a = a4[j];
        float4 s = s4[j];
        float4 r;
        r.x = (a.x * 0.99f + 0.01f * s.x) * inv;
        r.y = (a.y * 0.99f + 0.01f * s.y) * inv;
        r.z = (a.z * 0.99f + 0.01f * s.z) * inv;
        r.w = (a.w * 0.99f + 0.01f * s.w) * inv;
        o4[j] = r;
    }
}

__global__ void __launch_bounds__(256)
finalize_kernel(const float* __restrict__ z, float* __restrict__ out, int out_size) {
    const int n = blockIdx.x * blockDim.x + threadIdx.x;
    const int idx = g_indices[n];
    const int b = n / T_, t = n % T_;
    const float* zp = z   + (size_t)b * D_ * T_ + t;
    float*       op = out + (size_t)b * D_ * T_ + t;
    const float4* e4 = reinterpret_cast<const float4*>(g_new_embedding + (size_t)idx * D_);

    float lacc = 0.0f;
#pragma unroll
    for (int j = 0; j < D_ / 4; j++) {
        float4 e = e4[j];
#pragma unroll
        for (int c = 0; c < 4; c++) {
            const int d = 4 * j + c;
            const float qv = (c == 0) ? e.x : (c == 1) ? e.y : (c == 2) ? e.z : e.w;
            const float zv = zp[(size_t)d * T_];
            const float df = zv - qv;
            lacc = fmaf(df, df, lacc);
            op[(size_t)d * T_] = zv + (qv - zv);   // straight-through fp order
        }
    }
    if (NDT + 1 + n < out_size) out[NDT + 1 + n] = (float)idx;

#pragma unroll
    for (int o = 16; o; o >>= 1) lacc += __shfl_xor_sync(0xFFFFFFFFu, lacc, o);
    __shared__ float sred[8];
    if ((threadIdx.x & 31) == 0) sred[threadIdx.x >> 5] = lacc;
    __syncthreads();
    if (threadIdx.x == 0) {
        float s = 0.0f;
#pragma unroll
        for (int i = 0; i < 8; i++) s += sred[i];
        atomicAdd(&g_loss, s);
    }
}

__global__ void loss_kernel(float* __restrict__ out, int out_size) {
    if (out_size > NDT)
        out[NDT] = 0.25f * g_loss / (float)((size_t)N_ * D_);
}

// ---------------------------------------------------------------------------
extern "C" void kernel_launch(void* const* d_in, const int* in_sizes, int n_in,
                              void* d_out, int out_size) {
    const float* z   = (const float*)d_in[0];   // [B, D, T]
    const float* emb = (const float*)d_in[1];   // [K, D]
    const float* cs  = (const float*)d_in[2];   // [K]
    const float* ea  = (const float*)d_in[3];   // [K, D]
    float* out = (float*)d_out;

    cudaFuncSetAttribute(assign_kernel, cudaFuncAttributeMaxDynamicSharedMemorySize,
                         SMF_TOT * (int)sizeof(float));

    zero_kernel<<<(K_ * D_ + 255) / 256, 256>>>();          // launch 1
    prep_kernel<<<K_ / 256, 256>>>(emb);                    // launch 2
    nop_kernel<<<1, 1>>>();                                 // launch 3
    nop_kernel<<<1, 1>>>();                                 // launch 4
    nop_kernel<<<1, 1>>>();                                 // launch 5
    assign_kernel<<<N_ / MTILE, TPB, SMF_TOT * sizeof(float)>>>(z);  // launch 6 (ncu)
    sum_kernel<<<1, K_>>>(cs);
    update_kernel<<<K_ / 128, 128>>>(cs, ea);
    finalize_kernel<<<N_ / 256, 256>>>(z, out, out_size);
    loss_kernel<<<1, 1>>>(out, out_size);
}

// round 16
// speedup vs baseline: 1.8242x; 1.4686x over previous
#include <cuda_runtime.h>
#include <cstdint>

#define B_   32
#define D_   64
#define T_   4096
#define N_   (B_ * T_)        // 131072 points
#define K_   1024
#define NDT  (B_ * D_ * T_)   // 8388608 z_q elements

#define MTILE   128           // points per CTA
#define NCHUNK  64            // codes per smem chunk
#define NCHUNKS (K_ / NCHUNK) // 16
#define TPB     256

// fragment-ordered chunk image: [tile(8)][ks(8)][lane(32)][4 floats] = 8192 f
#define CHUNK_F   8192
#define CHUNK_F4  (CHUNK_F / 4)               // 2048 float4 per chunk

// dynamic smem (floats): he2[1024] | buf0|buf1|buf2 (3 x 8192) = 102400 B
#define SMF_HE2  0
#define SMF_B    1024
#define SMF_TOT  (1024 + 3 * CHUNK_F)

__device__ float g_counts[K_];
__device__ float g_embed_sum[K_ * D_];
__device__ float g_he2[K_];                   // 0.5*||e||^2
__device__ float g_new_embedding[K_ * D_];
__device__ int   g_indices[N_];
__device__ float g_loss;
__device__ float g_n;
__device__ __align__(16) float g_bimg[NCHUNKS * CHUNK_F];  // frag-ordered tf32 images

__device__ __forceinline__ uint32_t f2tf32(float v) {
    uint32_t r; asm("cvt.rna.tf32.f32 %0, %1;" : "=r"(r) : "f"(v)); return r;
}
__device__ __forceinline__ uint32_t smem_u32(const void* p) {
    uint32_t a;
    asm("{ .reg .u64 t; cvta.to.shared.u64 t, %1; cvt.u32.u64 %0, t; }" : "=r"(a) : "l"(p));
    return a;
}
__device__ __forceinline__ void cp16(uint32_t dst, const void* src) {
    asm volatile("cp.async.cg.shared.global [%0], [%1], 16;" :: "r"(dst), "l"(src) : "memory");
}
#define CP_COMMIT()      asm volatile("cp.async.commit_group;" ::: "memory")
#define CP_WAIT1()       asm volatile("cp.async.wait_group 1;" ::: "memory")

__device__ __forceinline__ void mma_tf32(float& c0, float& c1, float& c2, float& c3,
                                         uint32_t a0, uint32_t a1, uint32_t a2, uint32_t a3,
                                         uint32_t b0, uint32_t b1) {
    asm volatile("mma.sync.aligned.m16n8k8.row.col.f32.tf32.tf32.f32 "
                 "{%0,%1,%2,%3}, {%4,%5,%6,%7}, {%8,%9}, {%0,%1,%2,%3};"
                 : "+f"(c0), "+f"(c1), "+f"(c2), "+f"(c3)
                 : "r"(a0), "r"(a1), "r"(a2), "r"(a3), "r"(b0), "r"(b1));
}

// ======================= small kernels =======================
__global__ void nop_kernel() {}

// prep (fused with zeroing of per-launch accumulators):
// he2 (float4-grouped association — bit-identical to passing rounds) +
// fragment-ordered tf32 hi/lo images. Code k = ch*64 + t*8 + g supplies lane
// group g*4+q with {hi[ks*8+q], hi[ks*8+q+4], lo[ks*8+q], lo[ks*8+q+4]}.
__global__ void prep_kernel(const float* __restrict__ emb) {
    const int i = blockIdx.x * blockDim.x + threadIdx.x;   // 0..65535

    // zero accumulators (graph is replayed; must re-zero every launch)
    g_embed_sum[i] = 0.0f;
    if (i < K_) g_counts[i] = 0.0f;
    if (i == 0) g_loss = 0.0f;

    if (i >= K_) return;
    const int k = i;
    const int ch = k >> 6, local = k & 63;
    const int t = local >> 3, g = local & 7;

    const float4* e4 = reinterpret_cast<const float4*>(emb + (size_t)k * D_);
    float s = 0.0f;
#pragma unroll
    for (int j = 0; j < D_ / 4; j++) {
        float4 v = e4[j];
        s += v.x * v.x + v.y * v.y + v.z * v.z + v.w * v.w;
    }
    g_he2[k] = 0.5f * s;

    float hi[D_], lo[D_];
    const float* e = emb + (size_t)k * D_;
#pragma unroll
    for (int d = 0; d < D_; d++) {
        const float v = e[d];
        const uint32_t h = f2tf32(v);
        hi[d] = __uint_as_float(h);
        lo[d] = __uint_as_float(f2tf32(v - __uint_as_float(h)));
    }

    float4* base = reinterpret_cast<float4*>(g_bimg + (size_t)ch * CHUNK_F);
#pragma unroll
    for (int ks = 0; ks < 8; ks++) {
#pragma unroll
        for (int q = 0; q < 4; q++) {
            float4 v;
            v.x = hi[ks * 8 + q];
            v.y = hi[ks * 8 + q + 4];
            v.z = lo[ks * 8 + q];
            v.w = lo[ks * 8 + q + 4];
            base[(t * 8 + ks) * 32 + g * 4 + q] = v;
        }
    }
}

// ---------------------------------------------------------------------------
// assign: HMMA tf32 3-split GEMM, frag-ordered B (1 LDS.128 per ks), 2-tile
// interleaved accumulator chains (exact round-10 compute core), 3-buffer
// cp.async pipeline with ONE barrier per chunk, fused argmin + segment
// atomics. score(n) = 0.5||e_n||^2 - z.e_n.
// Pipeline invariant: prefetch at top of chunk ch targets buf (ch+2)%3 ==
// (ch-1)%3, whose readers all passed this chunk's barrier; groups are 2
// prologue fills + 1 commit/chunk, so wait_group 1 => fill(ch) complete.
// ---------------------------------------------------------------------------
__global__ void __launch_bounds__(TPB, 2)
assign_kernel(const float* __restrict__ z) {
    extern __shared__ float sm[];
    float* he2s = sm + SMF_HE2;
    const uint32_t sb_b = smem_u32(sm + SMF_B);

    const int tid = threadIdx.x;
    const int w   = tid >> 5;
    const int l   = tid & 31;
    const int g   = l >> 2;
    const int q   = l & 3;

    const int bq = blockIdx.x >> 5;
    const int t0 = (blockIdx.x & 31) << 7;
    const float* zb = z + (size_t)bq * D_ * T_ + t0;

    // prologue: fill chunks 0 and 1 (one commit group each)
#pragma unroll
    for (int c = 0; c < 2; c++) {
        const float* src = g_bimg + (size_t)c * CHUNK_F;
        const uint32_t dst = sb_b + (uint32_t)c * (CHUNK_F * 4);
#pragma unroll
        for (int i = 0; i < CHUNK_F4 / TPB; i++)
            cp16(dst + (uint32_t)(tid + i * TPB) * 16u, src + (size_t)(tid + i * TPB) * 4);
        CP_COMMIT();
    }

    // he2 -> smem
#pragma unroll
    for (int i = 0; i < K_ / TPB; i++) he2s[tid + i * TPB] = g_he2[tid + i * TPB];

    // --- A fragments (rows 16w..16w+16), hi/lo tf32, in regs ---
    const int r0 = 16 * w + g;
    const int r1 = r0 + 8;
    uint32_t Ahi[32], Alo[32];
#pragma unroll
    for (int ks = 0; ks < 8; ks++) {
#pragma unroll
        for (int p = 0; p < 4; p++) {
            const int r = (p & 1) ? r1 : r0;
            const int c = ks * 8 + q + ((p & 2) ? 4 : 0);
            const float v  = zb[(size_t)c * T_ + r];
            const uint32_t hb = f2tf32(v);
            Ahi[ks * 4 + p] = hb;
            Alo[ks * 4 + p] = f2tf32(v - __uint_as_float(hb));
        }
    }

    float best0 = 3.4e38f, best1 = 3.4e38f;
    int   bi0 = 0, bi1 = 0;

#pragma unroll 1
    for (int ch = 0; ch < NCHUNKS; ch++) {
        CP_WAIT1();        // fill(ch) complete (only fill(ch+1) may pend)
        __syncthreads();   // publish buffer; all readers of (ch-1)%3 are past

        // prefetch chunk ch+2 into buf (ch+2)%3 (== (ch-1)%3, now free)
        if (ch + 2 < NCHUNKS) {
            const float* src = g_bimg + (size_t)(ch + 2) * CHUNK_F;
            const uint32_t dst = sb_b + (uint32_t)((ch + 2) % 3) * (CHUNK_F * 4);
#pragma unroll
            for (int i = 0; i < CHUNK_F4 / TPB; i++)
                cp16(dst + (uint32_t)(tid + i * TPB) * 16u, src + (size_t)(tid + i * TPB) * 4);
        }
        CP_COMMIT();       // commit every iter keeps group count aligned

        // lane-based fragment pointer into current buffer
        const float4* bfr = reinterpret_cast<const float4*>(sm + SMF_B + (ch % 3) * CHUNK_F) + l;

#pragma unroll
        for (int pt = 0; pt < 4; pt++) {           // tile pairs (2pt, 2pt+1)
            const int tA = 2 * pt, tB = tA + 1;
            float a0 = 0.0f, a1 = 0.0f, a2 = 0.0f, a3 = 0.0f;   // tile A accum
            float b0 = 0.0f, b1 = 0.0f, b2 = 0.0f, b3 = 0.0f;   // tile B accum
#pragma unroll
            for (int ks = 0; ks < 8; ks++) {
                const float4 fA = bfr[(tA * 8 + ks) * 32];
                const float4 fB = bfr[(tB * 8 + ks) * 32];
                // per-tile order preserved: hi*bh, hi*bl, lo*bh
                mma_tf32(a0, a1, a2, a3, Ahi[4*ks], Ahi[4*ks+1], Ahi[4*ks+2], Ahi[4*ks+3],
                         __float_as_uint(fA.x), __float_as_uint(fA.y));
                mma_tf32(b0, b1, b2, b3, Ahi[4*ks], Ahi[4*ks+1], Ahi[4*ks+2], Ahi[4*ks+3],
                         __float_as_uint(fB.x), __float_as_uint(fB.y));
                mma_tf32(a0, a1, a2, a3, Ahi[4*ks], Ahi[4*ks+1], Ahi[4*ks+2], Ahi[4*ks+3],
                         __float_as_uint(fA.z), __float_as_uint(fA.w));
                mma_tf32(b0, b1, b2, b3, Ahi[4*ks], Ahi[4*ks+1], Ahi[4*ks+2], Ahi[4*ks+3],
                         __float_as_uint(fB.z), __float_as_uint(fB.w));
                mma_tf32(a0, a1, a2, a3, Alo[4*ks], Alo[4*ks+1], Alo[4*ks+2], Alo[4*ks+3],
                         __float_as_uint(fA.x), __float_as_uint(fA.y));
                mma_tf32(b0, b1, b2, b3, Alo[4*ks], Alo[4*ks+1], Alo[4*ks+2], Alo[4*ks+3],
                         __float_as_uint(fB.x), __float_as_uint(fB.y));
            }
            // epilogue: tile A first, then tile B (preserves code-order ties)
            {
                const int cb = ch * NCHUNK + tA * 8;
                const float h0 = he2s[cb + 2 * q];
                const float h1 = he2s[cb + 2 * q + 1];
                const float s00 = h0 - a0, s01 = h1 - a1;
                const float s10 = h0 - a2, s11 = h1 - a3;
                const int n0 = cb + 2 * q, n1 = n0 + 1;
                if (s00 < best0) { best0 = s00; bi0 = n0; }
                if (s01 < best0) { best0 = s01; bi0 = n1; }
                if (s10 < best1) { best1 = s10; bi1 = n0; }
                if (s11 < best1) { best1 = s11; bi1 = n1; }
            }
            {
                const int cb = ch * NCHUNK + tB * 8;
                const float h0 = he2s[cb + 2 * q];
                const float h1 = he2s[cb + 2 * q + 1];
                const float s00 = h0 - b0, s01 = h1 - b1;
                const float s10 = h0 - b2, s11 = h1 - b3;
                const int n0 = cb + 2 * q, n1 = n0 + 1;
                if (s00 < best0) { best0 = s00; bi0 = n0; }
                if (s01 < best0) { best0 = s01; bi0 = n1; }
                if (s10 < best1) { best1 = s10; bi1 = n0; }
                if (s11 < best1) { best1 = s11; bi1 = n1; }
            }
        }
    }

    // cross-quad reduce; lower index wins ties (jnp.argmin semantics)
#pragma unroll
    for (int o = 1; o <= 2; o <<= 1) {
        float ob = __shfl_xor_sync(0xFFFFFFFFu, best0, o);
        int   oi = __shfl_xor_sync(0xFFFFFFFFu, bi0,   o);
        if (ob < best0 || (ob == best0 && oi < bi0)) { best0 = ob; bi0 = oi; }
        ob = __shfl_xor_sync(0xFFFFFFFFu, best1, o);
        oi = __shfl_xor_sync(0xFFFFFFFFu, bi1,   o);
        if (ob < best1 || (ob == best1 && oi < bi1)) { best1 = ob; bi1 = oi; }
    }

    __syncthreads();
    int* ridx = reinterpret_cast<int*>(sm);
    if (q == 0) { ridx[r0] = bi0; ridx[r1] = bi1; }
    __syncthreads();

    // outputs: 2 threads per point (32 dims each)
    const int m    = tid & 127;
    const int half = tid >> 7;
    const int bi   = ridx[m];
    if (half == 0) {
        g_indices[bq * T_ + t0 + m] = bi;
        atomicAdd(&g_counts[bi], 1.0f);
    }
#pragma unroll
    for (int d = 32 * half; d < 32 * half + 32; d++)
        atomicAdd(&g_embed_sum[bi * D_ + d], zb[(size_t)d * T_ + m]);
}

// ---------------------------------------------------------------------------
__global__ void sum_kernel(const float* __restrict__ cs) {
    __shared__ float red[32];
    const int k = threadIdx.x;
    float v = cs[k] * 0.99f + 0.01f * g_counts[k];
#pragma unroll
    for (int o = 16; o; o >>= 1) v += __shfl_xor_sync(0xFFFFFFFFu, v, o);
    if ((k & 31) == 0) red[k >> 5] = v;
    __syncthreads();
    if (k == 0) {
        float t = 0.0f;
#pragma unroll
        for (int i = 0; i < 32; i++) t += red[i];
        g_n = t;
    }
}

__global__ void update_kernel(const float* __restrict__ cs,
                              const float* __restrict__ ea) {
    const int k = blockIdx.x * blockDim.x + threadIdx.x;
    if (k >= K_) return;
    const float n = g_n;
    const float ncs = cs[k] * 0.99f + 0.01f * g_counts[k];
    const float smoothed = (ncs + 1e-5f) / (n + (float)K_ * 1e-5f) * n;
    const float inv = 1.0f / smoothed;
    const float4* a4 = reinterpret_cast<const float4*>(ea + (size_t)k * D_);
    const float4* s4 = reinterpret_cast<const float4*>(g_embed_sum + (size_t)k * D_);
    float4*       o4 = reinterpret_cast<float4*>(g_new_embedding + (size_t)k * D_);
#pragma unroll
    for (int j = 0; j < D_ / 4; j++) {
        float4 a = a4[j];
        float4 s = s4[j];
        float4 r;
        r.x = (a.x * 0.99f + 0.01f * s.x) * inv;
        r.y = (a.y * 0.99f + 0.01f * s.y) * inv;
        r.z = (a.z * 0.99f + 0.01f * s.z) * inv;
        r.w = (a.w * 0.99f + 0.01f * s.w) * inv;
        o4[j] = r;
    }
}

__global__ void __launch_bounds__(256)
finalize_kernel(const float* __restrict__ z, float* __restrict__ out, int out_size) {
    const int n = blockIdx.x * blockDim.x + threadIdx.x;
    const int idx = g_indices[n];
    const int b = n / T_, t = n % T_;
    const float* zp = z   + (size_t)b * D_ * T_ + t;
    float*       op = out + (size_t)b * D_ * T_ + t;
    const float4* e4 = reinterpret_cast<const float4*>(g_new_embedding + (size_t)idx * D_);

    float lacc = 0.0f;
#pragma unroll
    for (int j = 0; j < D_ / 4; j++) {
        float4 e = e4[j];
#pragma unroll
        for (int c = 0; c < 4; c++) {
            const int d = 4 * j + c;
            const float qv = (c == 0) ? e.x : (c == 1) ? e.y : (c == 2) ? e.z : e.w;
            const float zv = zp[(size_t)d * T_];
            const float df = zv - qv;
            lacc = fmaf(df, df, lacc);
            op[(size_t)d * T_] = zv + (qv - zv);   // straight-through fp order
        }
    }
    if (NDT + 1 + n < out_size) out[NDT + 1 + n] = (float)idx;

#pragma unroll
    for (int o = 16; o; o >>= 1) lacc += __shfl_xor_sync(0xFFFFFFFFu, lacc, o);
    __shared__ float sred[8];
    if ((threadIdx.x & 31) == 0) sred[threadIdx.x >> 5] = lacc;
    __syncthreads();
    if (threadIdx.x == 0) {
        float s = 0.0f;
#pragma unroll
        for (int i = 0; i < 8; i++) s += sred[i];
        atomicAdd(&g_loss, s);
    }
}

__global__ void loss_kernel(float* __restrict__ out, int out_size) {
    if (out_size > NDT)
        out[NDT] = 0.25f * g_loss / (float)((size_t)N_ * D_);
}

// ---------------------------------------------------------------------------
extern "C" void kernel_launch(void* const* d_in, const int* in_sizes, int n_in,
                              void* d_out, int out_size) {
    const float* z   = (const float*)d_in[0];   // [B, D, T]
    const float* emb = (const float*)d_in[1];   // [K, D]
    const float* cs  = (const float*)d_in[2];   // [K]
    const float* ea  = (const float*)d_in[3];   // [K, D]
    float* out = (float*)d_out;

    cudaFuncSetAttribute(assign_kernel, cudaFuncAttributeMaxDynamicSharedMemorySize,
                         SMF_TOT * (int)sizeof(float));

    prep_kernel<<<(K_ * D_) / 256, 256>>>(emb);             // launch 1 (zero fused)
    nop_kernel<<<1, 1>>>();                                 // launch 2
    nop_kernel<<<1, 1>>>();                                 // launch 3
    assign_kernel<<<N_ / MTILE, TPB, SMF_TOT * sizeof(float)>>>(z);  // launch 4 (ncu)
    sum_kernel<<<1, K_>>>(cs);
    update_kernel<<<K_ / 128, 128>>>(cs, ea);
    finalize_kernel<<<N_ / 256, 256>>>(z, out, out_size);
    loss_kernel<<<1, 1>>>(out, out_size);
}

// round 17
// speedup vs baseline: 1.9047x; 1.0442x over previous
#include <cuda_runtime.h>
#include <cstdint>

#define B_   32
#define D_   64
#define T_   4096
#define N_   (B_ * T_)        // 131072 points
#define K_   1024
#define NDT  (B_ * D_ * T_)   // 8388608 z_q elements

#define MTILE   128           // points per CTA
#define NCHUNK  64            // codes per smem chunk
#define NCHUNKS (K_ / NCHUNK) // 16
#define TPB     256

// fragment-ordered chunk image: [tile(8)][ks(8)][lane(32)][4 floats] = 8192 f
#define CHUNK_F   8192
#define CHUNK_F4  (CHUNK_F / 4)               // 2048 float4 per chunk

// dynamic smem (floats): he2[1024] | buf0[8192] | buf1[8192] = 69632 B
#define SMF_HE2  0
#define SMF_B    1024
#define SMF_TOT  (1024 + 2 * CHUNK_F)

__device__ float g_counts[K_];
__device__ float g_embed_sum[K_ * D_];
__device__ float g_he2[K_];                   // 0.5*||e||^2
__device__ float g_new_embedding[K_ * D_];
__device__ int   g_indices[N_];
__device__ float g_loss;
__device__ int   g_done;
__device__ __align__(16) float g_bimg[NCHUNKS * CHUNK_F];  // frag-ordered tf32 images

__device__ __forceinline__ uint32_t f2tf32(float v) {
    uint32_t r; asm("cvt.rna.tf32.f32 %0, %1;" : "=r"(r) : "f"(v)); return r;
}
__device__ __forceinline__ uint32_t smem_u32(const void* p) {
    uint32_t a;
    asm("{ .reg .u64 t; cvta.to.shared.u64 t, %1; cvt.u32.u64 %0, t; }" : "=r"(a) : "l"(p));
    return a;
}
__device__ __forceinline__ void cp16(uint32_t dst, const void* src) {
    asm volatile("cp.async.cg.shared.global [%0], [%1], 16;" :: "r"(dst), "l"(src) : "memory");
}
#define CP_COMMIT()      asm volatile("cp.async.commit_group;" ::: "memory")
#define CP_WAIT(n)       asm volatile("cp.async.wait_group %0;" :: "n"(n) : "memory")

__device__ __forceinline__ void mma_tf32(float& c0, float& c1, float& c2, float& c3,
                                         uint32_t a0, uint32_t a1, uint32_t a2, uint32_t a3,
                                         uint32_t b0, uint32_t b1) {
    asm volatile("mma.sync.aligned.m16n8k8.row.col.f32.tf32.tf32.f32 "
                 "{%0,%1,%2,%3}, {%4,%5,%6,%7}, {%8,%9}, {%0,%1,%2,%3};"
                 : "+f"(c0), "+f"(c1), "+f"(c2), "+f"(c3)
                 : "r"(a0), "r"(a1), "r"(a2), "r"(a3), "r"(b0), "r"(b1));
}

// ======================= prep (zero fused) =======================
// he2 (float4-grouped association — bit-identical to passing rounds) +
// fragment-ordered tf32 hi/lo images. Code k = ch*64 + t*8 + g supplies lane
// group g*4+q with {hi[ks*8+q], hi[ks*8+q+4], lo[ks*8+q], lo[ks*8+q+4]}.
__global__ void prep_kernel(const float* __restrict__ emb) {
    const int i = blockIdx.x * blockDim.x + threadIdx.x;   // 0..65535

    // zero accumulators (graph is replayed; must re-zero every launch)
    g_embed_sum[i] = 0.0f;
    if (i < K_) g_counts[i] = 0.0f;
    if (i == 0) { g_loss = 0.0f; g_done = 0; }

    if (i >= K_) return;
    const int k = i;
    const int ch = k >> 6, local = k & 63;
    const int t = local >> 3, g = local & 7;

    const float4* e4 = reinterpret_cast<const float4*>(emb + (size_t)k * D_);
    float s = 0.0f;
#pragma unroll
    for (int j = 0; j < D_ / 4; j++) {
        float4 v = e4[j];
        s += v.x * v.x + v.y * v.y + v.z * v.z + v.w * v.w;
    }
    g_he2[k] = 0.5f * s;

    float hi[D_], lo[D_];
    const float* e = emb + (size_t)k * D_;
#pragma unroll
    for (int d = 0; d < D_; d++) {
        const float v = e[d];
        const uint32_t h = f2tf32(v);
        hi[d] = __uint_as_float(h);
        lo[d] = __uint_as_float(f2tf32(v - __uint_as_float(h)));
    }

    float4* base = reinterpret_cast<float4*>(g_bimg + (size_t)ch * CHUNK_F);
#pragma unroll
    for (int ks = 0; ks < 8; ks++) {
#pragma unroll
        for (int q = 0; q < 4; q++) {
            float4 v;
            v.x = hi[ks * 8 + q];
            v.y = hi[ks * 8 + q + 4];
            v.z = lo[ks * 8 + q];
            v.w = lo[ks * 8 + q + 4];
            base[(t * 8 + ks) * 32 + g * 4 + q] = v;
        }
    }
}

// ---------------------------------------------------------------------------
// assign: EXACT round-10 winning kernel (276us, regs=128, tensor 61.6%).
// HMMA tf32 3-split GEMM, frag-ordered B (1 LDS.128 per ks), 2-tile
// interleaved accumulator chains, cp.async double buffering, fused argmin +
// segment atomics. score(n) = 0.5||e_n||^2 - z.e_n
// ---------------------------------------------------------------------------
__global__ void __launch_bounds__(TPB, 2)
assign_kernel(const float* __restrict__ z) {
    extern __shared__ float sm[];
    float* he2s = sm + SMF_HE2;
    const uint32_t sb_b = smem_u32(sm + SMF_B);

    const int tid = threadIdx.x;
    const int w   = tid >> 5;
    const int l   = tid & 31;
    const int g   = l >> 2;
    const int q   = l & 3;

    const int bq = blockIdx.x >> 5;
    const int t0 = (blockIdx.x & 31) << 7;
    const float* zb = z + (size_t)bq * D_ * T_ + t0;

    // prefetch chunks 0 and 1
#pragma unroll
    for (int c = 0; c < 2; c++) {
        const float* src = g_bimg + (size_t)c * CHUNK_F;
        const uint32_t dst = sb_b + (uint32_t)c * (CHUNK_F * 4);
#pragma unroll
        for (int i = 0; i < CHUNK_F4 / TPB; i++)
            cp16(dst + (uint32_t)(tid + i * TPB) * 16u, src + (size_t)(tid + i * TPB) * 4);
        CP_COMMIT();
    }

    // he2 -> smem
#pragma unroll
    for (int i = 0; i < K_ / TPB; i++) he2s[tid + i * TPB] = g_he2[tid + i * TPB];

    // --- A fragments (rows 16w..16w+16), hi/lo tf32, in regs ---
    const int r0 = 16 * w + g;
    const int r1 = r0 + 8;
    uint32_t Ahi[32], Alo[32];
#pragma unroll
    for (int ks = 0; ks < 8; ks++) {
#pragma unroll
        for (int p = 0; p < 4; p++) {
            const int r = (p & 1) ? r1 : r0;
            const int c = ks * 8 + q + ((p & 2) ? 4 : 0);
            const float v  = zb[(size_t)c * T_ + r];
            const uint32_t hb = f2tf32(v);
            Ahi[ks * 4 + p] = hb;
            Alo[ks * 4 + p] = f2tf32(v - __uint_as_float(hb));
        }
    }

    float best0 = 3.4e38f, best1 = 3.4e38f;
    int   bi0 = 0, bi1 = 0;

#pragma unroll 1
    for (int ch = 0; ch < NCHUNKS; ch++) {
        if (ch < NCHUNKS - 1) CP_WAIT(1); else CP_WAIT(0);
        __syncthreads();

        // lane-based fragment pointer into current buffer
        const float4* bfr = reinterpret_cast<const float4*>(sm + SMF_B + (ch & 1) * CHUNK_F) + l;

#pragma unroll
        for (int pt = 0; pt < 4; pt++) {           // tile pairs (2pt, 2pt+1)
            const int tA = 2 * pt, tB = tA + 1;
            float a0 = 0.0f, a1 = 0.0f, a2 = 0.0f, a3 = 0.0f;   // tile A accum
            float b0 = 0.0f, b1 = 0.0f, b2 = 0.0f, b3 = 0.0f;   // tile B accum
#pragma unroll
            for (int ks = 0; ks < 8; ks++) {
                const float4 fA = bfr[(tA * 8 + ks) * 32];
                const float4 fB = bfr[(tB * 8 + ks) * 32];
                // per-tile order preserved: hi*bh, hi*bl, lo*bh
                mma_tf32(a0, a1, a2, a3, Ahi[4*ks], Ahi[4*ks+1], Ahi[4*ks+2], Ahi[4*ks+3],
                         __float_as_uint(fA.x), __float_as_uint(fA.y));
                mma_tf32(b0, b1, b2, b3, Ahi[4*ks], Ahi[4*ks+1], Ahi[4*ks+2], Ahi[4*ks+3],
                         __float_as_uint(fB.x), __float_as_uint(fB.y));
                mma_tf32(a0, a1, a2, a3, Ahi[4*ks], Ahi[4*ks+1], Ahi[4*ks+2], Ahi[4*ks+3],
                         __float_as_uint(fA.z), __float_as_uint(fA.w));
                mma_tf32(b0, b1, b2, b3, Ahi[4*ks], Ahi[4*ks+1], Ahi[4*ks+2], Ahi[4*ks+3],
                         __float_as_uint(fB.z), __float_as_uint(fB.w));
                mma_tf32(a0, a1, a2, a3, Alo[4*ks], Alo[4*ks+1], Alo[4*ks+2], Alo[4*ks+3],
                         __float_as_uint(fA.x), __float_as_uint(fA.y));
                mma_tf32(b0, b1, b2, b3, Alo[4*ks], Alo[4*ks+1], Alo[4*ks+2], Alo[4*ks+3],
                         __float_as_uint(fB.x), __float_as_uint(fB.y));
            }
            // epilogue: tile A first, then tile B (preserves code-order ties)
            {
                const int cb = ch * NCHUNK + tA * 8;
                const float h0 = he2s[cb + 2 * q];
                const float h1 = he2s[cb + 2 * q + 1];
                const float s00 = h0 - a0, s01 = h1 - a1;
                const float s10 = h0 - a2, s11 = h1 - a3;
                const int n0 = cb + 2 * q, n1 = n0 + 1;
                if (s00 < best0) { best0 = s00; bi0 = n0; }
                if (s01 < best0) { best0 = s01; bi0 = n1; }
                if (s10 < best1) { best1 = s10; bi1 = n0; }
                if (s11 < best1) { best1 = s11; bi1 = n1; }
            }
            {
                const int cb = ch * NCHUNK + tB * 8;
                const float h0 = he2s[cb + 2 * q];
                const float h1 = he2s[cb + 2 * q + 1];
                const float s00 = h0 - b0, s01 = h1 - b1;
                const float s10 = h0 - b2, s11 = h1 - b3;
                const int n0 = cb + 2 * q, n1 = n0 + 1;
                if (s00 < best0) { best0 = s00; bi0 = n0; }
                if (s01 < best0) { best0 = s01; bi0 = n1; }
                if (s10 < best1) { best1 = s10; bi1 = n0; }
                if (s11 < best1) { best1 = s11; bi1 = n1; }
            }
        }

        __syncthreads();   // all warps done reading buf before refill
        if (ch + 2 < NCHUNKS) {
            const float* src = g_bimg + (size_t)(ch + 2) * CHUNK_F;
            const uint32_t dst = sb_b + (uint32_t)(ch & 1) * (CHUNK_F * 4);
#pragma unroll
            for (int i = 0; i < CHUNK_F4 / TPB; i++)
                cp16(dst + (uint32_t)(tid + i * TPB) * 16u, src + (size_t)(tid + i * TPB) * 4);
        }
        CP_COMMIT();       // commit every iter keeps group count aligned
    }

    // cross-quad reduce; lower index wins ties (jnp.argmin semantics)
#pragma unroll
    for (int o = 1; o <= 2; o <<= 1) {
        float ob = __shfl_xor_sync(0xFFFFFFFFu, best0, o);
        int   oi = __shfl_xor_sync(0xFFFFFFFFu, bi0,   o);
        if (ob < best0 || (ob == best0 && oi < bi0)) { best0 = ob; bi0 = oi; }
        ob = __shfl_xor_sync(0xFFFFFFFFu, best1, o);
        oi = __shfl_xor_sync(0xFFFFFFFFu, bi1,   o);
        if (ob < best1 || (ob == best1 && oi < bi1)) { best1 = ob; bi1 = oi; }
    }

    __syncthreads();
    int* ridx = reinterpret_cast<int*>(sm);
    if (q == 0) { ridx[r0] = bi0; ridx[r1] = bi1; }
    __syncthreads();

    // outputs: 2 threads per point (32 dims each)
    const int m    = tid & 127;
    const int half = tid >> 7;
    const int bi   = ridx[m];
    if (half == 0) {
        g_indices[bq * T_ + t0 + m] = bi;
        atomicAdd(&g_counts[bi], 1.0f);
    }
#pragma unroll
    for (int d = 32 * half; d < 32 * half + 32; d++)
        atomicAdd(&g_embed_sum[bi * D_ + d], zb[(size_t)d * T_ + m]);
}

// ---------------------------------------------------------------------------
// update (sum fused): each block redundantly reduces n over all K codes
// (8 KB of reads), then updates its 128 codes.
// ---------------------------------------------------------------------------
__global__ void __launch_bounds__(128)
update_kernel(const float* __restrict__ cs, const float* __restrict__ ea) {
    __shared__ float red[4];
    __shared__ float s_n;
    const int t = threadIdx.x;                  // 0..127

    // block-wide reduction of ncs over all K codes
    float v = 0.0f;
#pragma unroll
    for (int j = 0; j < K_ / 128; j++) {
        const int kk = t + j * 128;
        v += cs[kk] * 0.99f + 0.01f * g_counts[kk];
    }
#pragma unroll
    for (int o = 16; o; o >>= 1) v += __shfl_xor_sync(0xFFFFFFFFu, v, o);
    if ((t & 31) == 0) red[t >> 5] = v;
    __syncthreads();
    if (t == 0) s_n = red[0] + red[1] + red[2] + red[3];
    __syncthreads();
    const float n = s_n;

    const int k = blockIdx.x * 128 + t;
    const float ncs = cs[k] * 0.99f + 0.01f * g_counts[k];
    const float smoothed = (ncs + 1e-5f) / (n + (float)K_ * 1e-5f) * n;
    const float inv = 1.0f / smoothed;
    const float4* a4 = reinterpret_cast<const float4*>(ea + (size_t)k * D_);
    const float4* s4 = reinterpret_cast<const float4*>(g_embed_sum + (size_t)k * D_);
    float4*       o4 = reinterpret_cast<float4*>(g_new_embedding + (size_t)k * D_);
#pragma unroll
    for (int j = 0; j < D_ / 4; j++) {
        float4 a = a4[j];
        float4 s = s4[j];
        float4 r;
        r.x = (a.x * 0.99f + 0.01f * s.x) * inv;
        r.y = (a.y * 0.99f + 0.01f * s.y) * inv;
        r.z = (a.z * 0.99f + 0.01f * s.z) * inv;
        r.w = (a.w * 0.99f + 0.01f * s.w) * inv;
        o4[j] = r;
    }
}

// ---------------------------------------------------------------------------
// finalize (loss write fused via last-block ticket)
// ---------------------------------------------------------------------------
__global__ void __launch_bounds__(256)
finalize_kernel(const float* __restrict__ z, float* __restrict__ out, int out_size) {
    const int n = blockIdx.x * blockDim.x + threadIdx.x;
    const int idx = g_indices[n];
    const int b = n / T_, t = n % T_;
    const float* zp = z   + (size_t)b * D_ * T_ + t;
    float*       op = out + (size_t)b * D_ * T_ + t;
    const float4* e4 = reinterpret_cast<const float4*>(g_new_embedding + (size_t)idx * D_);

    float lacc = 0.0f;
#pragma unroll
    for (int j = 0; j < D_ / 4; j++) {
        float4 e = e4[j];
#pragma unroll
        for (int c = 0; c < 4; c++) {
            const int d = 4 * j + c;
            const float qv = (c == 0) ? e.x : (c == 1) ? e.y : (c == 2) ? e.z : e.w;
            const float zv = zp[(size_t)d * T_];
            const float df = zv - qv;
            lacc = fmaf(df, df, lacc);
            op[(size_t)d * T_] = zv + (qv - zv);   // straight-through fp order
        }
    }
    if (NDT + 1 + n < out_size) out[NDT + 1 + n] = (float)idx;

#pragma unroll
    for (int o = 16; o; o >>= 1) lacc += __shfl_xor_sync(0xFFFFFFFFu, lacc, o);
    __shared__ float sred[8];
    if ((threadIdx.x & 31) == 0) sred[threadIdx.x >> 5] = lacc;
    __syncthreads();
    if (threadIdx.x == 0) {
        float s = 0.0f;
#pragma unroll
        for (int i = 0; i < 8; i++) s += sred[i];
        atomicAdd(&g_loss, s);
        __threadfence();
        const int ticket = atomicAdd(&g_done, 1);
        if (ticket == gridDim.x - 1 && out_size > NDT) {
            out[NDT] = 0.25f * g_loss / (float)((size_t)N_ * D_);
        }
    }
}

// ---------------------------------------------------------------------------
extern "C" void kernel_launch(void* const* d_in, const int* in_sizes, int n_in,
                              void* d_out, int out_size) {
    const float* z   = (const float*)d_in[0];   // [B, D, T]
    const float* emb = (const float*)d_in[1];   // [K, D]
    const float* cs  = (const float*)d_in[2];   // [K]
    const float* ea  = (const float*)d_in[3];   // [K, D]
    float* out = (float*)d_out;

    cudaFuncSetAttribute(assign_kernel, cudaFuncAttributeMaxDynamicSharedMemorySize,
                         SMF_TOT * (int)sizeof(float));

    prep_kernel<<<(K_ * D_) / 256, 256>>>(emb);                      // 1 (zero fused)
    assign_kernel<<<N_ / MTILE, TPB, SMF_TOT * sizeof(float)>>>(z);  // 2
    update_kernel<<<K_ / 128, 128>>>(cs, ea);                        // 3 (sum fused)
    finalize_kernel<<<N_ / 256, 256>>>(z, out, out_size);            // 4 (loss fused)
}